// round 3
// baseline (speedup 1.0000x reference)
#include <cuda_runtime.h>

// ScaledDotProductAttention: B=4,H=16,S=2048,D=64 fp32, mask int32 [B,1,S,S].
// Outputs: out [B,H,S,D] followed by attn [B,H,S,S] in d_out (reference returns a tuple).

#define NB 4
#define NH 16
#define NS 2048
#define ND 64
#define ROWS 16          // q rows per CTA
#define CT 256           // k/v tile columns
#define NTH 512
#define NEGI (-1e14f)

__global__ __launch_bounds__(NTH, 1)
void sdpa_kernel(const float* __restrict__ Q, const float* __restrict__ K,
                 const float* __restrict__ V, const int* __restrict__ mask,
                 float* __restrict__ out, float* __restrict__ attn)
{
    extern __shared__ float sm[];
    float* sS  = sm;                   // ROWS*NS   = 32768 floats (128 KB) scores/P
    float* sKV = sS + ROWS * NS;       // CT*ND     = 16384 floats (64 KB)  K^T / V tile / reduce
    float* sQ  = sKV + CT * ND;        // ROWS*ND   = 1024 floats  (4 KB)   Q tile

    const int t  = threadIdx.x;
    const int bh = blockIdx.y;
    const int b  = bh >> 4;            // bh / NH
    const int q0 = blockIdx.x * ROWS;

    // ---- load Q tile (16x64) ----
    if (t < ROWS * ND / 4)
        ((float4*)sQ)[t] = ((const float4*)(Q + ((size_t)bh * NS + q0) * ND))[t];

    const int tx = t & 127;            // QK: col group
    const int ty = t >> 7;             // QK: row group (0..3)
    const int c0 = tx * 2;             // 2 local cols per thread
    const int lt = t & 15;             // loader: d-quad index
    const int ck = t >> 4;             // loader: base row/col (0..31)

    // =======================  Phase 1: scores = mask(scale * Q K^T)  =======================
    for (int ct = 0; ct < NS / CT; ++ct) {
        __syncthreads();               // previous tile fully consumed
        {   // load K tile [256 cols][64 d], stored d-major with XOR swizzle (d & 30)
            const float4* K4 = (const float4*)(K + ((size_t)bh * NS + (size_t)ct * CT) * ND);
            const int d0 = lt * 4;
            #pragma unroll
            for (int kk = 0; kk < 8; ++kk) {
                const int c = ck + kk * 32;
                float4 kv = K4[c * 16 + lt];
                sKV[(d0 + 0) * CT + (c ^ ((d0 + 0) & 30))] = kv.x;
                sKV[(d0 + 1) * CT + (c ^ ((d0 + 1) & 30))] = kv.y;
                sKV[(d0 + 2) * CT + (c ^ ((d0 + 2) & 30))] = kv.z;
                sKV[(d0 + 3) * CT + (c ^ ((d0 + 3) & 30))] = kv.w;
            }
        }
        __syncthreads();

        float a0[4], a1[4];
        #pragma unroll
        for (int rr = 0; rr < 4; ++rr) { a0[rr] = 0.f; a1[rr] = 0.f; }

        #pragma unroll
        for (int d4 = 0; d4 < 16; ++d4) {
            float qv[4][4];
            #pragma unroll
            for (int rr = 0; rr < 4; ++rr) {
                float4 qt = ((const float4*)sQ)[(ty * 4 + rr) * 16 + d4];
                qv[rr][0] = qt.x; qv[rr][1] = qt.y; qv[rr][2] = qt.z; qv[rr][3] = qt.w;
            }
            #pragma unroll
            for (int j = 0; j < 4; ++j) {
                const int dd = d4 * 4 + j;
                // c0 even, swizzle constant even -> the (c0, c0+1) pair stays adjacent
                const float2 kf = *(const float2*)&sKV[dd * CT + (c0 ^ (dd & 30))];
                #pragma unroll
                for (int rr = 0; rr < 4; ++rr) {
                    a0[rr] = fmaf(qv[rr][j], kf.x, a0[rr]);
                    a1[rr] = fmaf(qv[rr][j], kf.y, a1[rr]);
                }
            }
        }

        const int cg = ct * CT + c0;
        #pragma unroll
        for (int rr = 0; rr < 4; ++rr) {
            const int r = ty * 4 + rr;
            const int2 mm = *(const int2*)(mask + ((size_t)b * NS + (q0 + r)) * NS + cg);
            float2 sv;
            sv.x = (mm.x == 0) ? NEGI : a0[rr] * 0.125f;
            sv.y = (mm.y == 0) ? NEGI : a1[rr] * 0.125f;
            *(float2*)(sS + r * NS + cg) = sv;
        }
    }
    __syncthreads();

    // =======================  Phase 2: softmax, warp per row  =======================
    {
        const int w = t >> 5, l = t & 31;          // 16 warps == 16 rows
        float4 e[16];
        float mx = -3.4e38f;
        const float4* row4 = (const float4*)(sS + w * NS);
        #pragma unroll
        for (int i = 0; i < 16; ++i) {
            e[i] = row4[l + 32 * i];
            mx = fmaxf(mx, fmaxf(fmaxf(e[i].x, e[i].y), fmaxf(e[i].z, e[i].w)));
        }
        #pragma unroll
        for (int o = 16; o > 0; o >>= 1) mx = fmaxf(mx, __shfl_xor_sync(0xffffffffu, mx, o));
        float sum = 0.f;
        #pragma unroll
        for (int i = 0; i < 16; ++i) {
            e[i].x = __expf(e[i].x - mx);
            e[i].y = __expf(e[i].y - mx);
            e[i].z = __expf(e[i].z - mx);
            e[i].w = __expf(e[i].w - mx);
            sum += (e[i].x + e[i].y) + (e[i].z + e[i].w);
        }
        #pragma unroll
        for (int o = 16; o > 0; o >>= 1) sum += __shfl_xor_sync(0xffffffffu, sum, o);
        const float inv = 1.f / sum;
        float4* w4 = (float4*)(sS + w * NS);
        float4* a4 = attn ? (float4*)(attn + ((size_t)bh * NS + q0 + w) * NS) : (float4*)0;
        #pragma unroll
        for (int i = 0; i < 16; ++i) {
            float4 p = e[i];
            p.x *= inv; p.y *= inv; p.z *= inv; p.w *= inv;
            w4[l + 32 * i] = p;                    // normalized P back to smem (for PV)
            if (a4) a4[l + 32 * i] = p;            // attn output, coalesced float4
        }
    }

    // =======================  Phase 3: out = P @ V  =======================
    const int g  = t >> 7;        // k-quarter within each tile (0..3)
    const int u  = t & 127;
    const int ln = u & 31;        // d pair: d = 2*ln
    const int ry = u >> 5;        // row group (0..3): rows ry*4 .. ry*4+3
    float2 acc[4];
    #pragma unroll
    for (int rr = 0; rr < 4; ++rr) acc[rr] = make_float2(0.f, 0.f);

    for (int ct = 0; ct < NS / CT; ++ct) {
        __syncthreads();
        {   // load V tile [256 k][64 d], k-major (straight copy)
            const float4* V4 = (const float4*)(V + ((size_t)bh * NS + (size_t)ct * CT) * ND);
            #pragma unroll
            for (int kk = 0; kk < 8; ++kk) {
                const int k = ck + kk * 32;
                ((float4*)sKV)[k * 16 + lt] = V4[k * 16 + lt];
            }
        }
        __syncthreads();

        const int kb0 = g * 64;
        #pragma unroll 4
        for (int kb = 0; kb < 64; kb += 4) {
            const int k = kb0 + kb;
            float pv[4][4];
            #pragma unroll
            for (int rr = 0; rr < 4; ++rr) {
                float4 p = *(const float4*)(sS + (ry * 4 + rr) * NS + ct * CT + k);
                pv[rr][0] = p.x; pv[rr][1] = p.y; pv[rr][2] = p.z; pv[rr][3] = p.w;
            }
            #pragma unroll
            for (int j = 0; j < 4; ++j) {
                const float2 v = *(const float2*)(sKV + (k + j) * ND + ln * 2);
                #pragma unroll
                for (int rr = 0; rr < 4; ++rr) {
                    acc[rr].x = fmaf(pv[rr][j], v.x, acc[rr].x);
                    acc[rr].y = fmaf(pv[rr][j], v.y, acc[rr].y);
                }
            }
        }
    }

    // reduce the 4 k-quarter partials through smem, then store out
    __syncthreads();                                // everyone done reading sKV as V
    #pragma unroll
    for (int rr = 0; rr < 4; ++rr)
        *(float2*)(sKV + g * 1024 + (ry * 4 + rr) * ND + ln * 2) = acc[rr];
    __syncthreads();
    {
        const int i = t * 2;                        // 512 threads x 2 floats = 1024 outputs
        const int r = i >> 6;
        const int d = i & 63;
        float2 s = *(const float2*)(sKV + i);
        #pragma unroll
        for (int gg = 1; gg < 4; ++gg) {
            float2 v = *(const float2*)(sKV + gg * 1024 + i);
            s.x += v.x; s.y += v.y;
        }
        *(float2*)(out + ((size_t)bh * NS + q0 + r) * ND + d) = s;
    }
}

extern "C" void kernel_launch(void* const* d_in, const int* in_sizes, int n_in,
                              void* d_out, int out_size)
{
    const float* Q    = (const float*)d_in[0];
    const float* K    = (const float*)d_in[1];
    const float* V    = (const float*)d_in[2];
    const int*   mask = (const int*)d_in[3];
    float* out = (float*)d_out;

    const long long OUT_E  = (long long)NB * NH * NS * ND;           // 8388608
    const long long ATTN_E = (long long)NB * NH * NS * (long long)NS; // 268435456
    float* attn = ((long long)out_size >= OUT_E + ATTN_E) ? out + OUT_E : (float*)0;

    const int smem = (ROWS * NS + CT * ND + ROWS * ND) * (int)sizeof(float); // 200704 B
    cudaFuncSetAttribute(sdpa_kernel, cudaFuncAttributeMaxDynamicSharedMemorySize, smem);

    dim3 grid(NS / ROWS, NB * NH);   // q-tile fastest -> one head's 128 CTAs co-resident (L2 reuse of K/V/mask)
    sdpa_kernel<<<grid, NTH, smem>>>(Q, K, V, mask, out, attn);
}